// round 10
// baseline (speedup 1.0000x reference)
#include <cuda_runtime.h>
#include <cuda_bf16.h>
#include <cstdint>

// Problem constants
#define TSTEPS 8
#define NB 64
#define NS 32
#define NBS 2048          // B*S
#define NK 3136           // DS == DT
#define NF 512
#define NH 512
#define NL 18
#define KSB 7             // split-K for basal GEMM
#define KCH_B 448         // 3136 / 7 (multiple of 32)
#define KSA 2             // split-K for apical GEMM
#define KCH_A 1568        // 3136 / 2

// ---------------- scratch (__device__ globals; no allocation allowed) -------
__device__ float g_apical[KSA * TSTEPS * NBS * NF];  // 67 MB (2 partials)
__device__ float g_bpart[KSB * TSTEPS * NB * NF];
__device__ float g_mball[TSTEPS * NB * NF];          // precomputed mb(t)
__device__ __align__(16) __nv_bfloat16 g_spall[TSTEPS * NBS * NF];  // all spikes
__device__ float g_hall[TSTEPS * NBS * NH];          // 67 MB
// bf16 hi/lo splits (weights only)
__device__ __align__(16) __nv_bfloat16 g_Wah[NF * NK];
__device__ __align__(16) __nv_bfloat16 g_Wal[NF * NK];
__device__ __align__(16) __nv_bfloat16 g_Wbh[NF * NK];
__device__ __align__(16) __nv_bfloat16 g_Wbl[NF * NK];
__device__ __align__(16) __nv_bfloat16 g_W1h[NH * NF];
__device__ __align__(16) __nv_bfloat16 g_W1l[NH * NF];

// ============================ PTX helpers ==================================
__device__ __forceinline__ uint32_t s2u(const void* p) {
    uint32_t a;
    asm("{ .reg .u64 t; cvta.to.shared.u64 t, %1; cvt.u32.u64 %0, t; }"
        : "=r"(a) : "l"(p));
    return a;
}
__device__ __forceinline__ void cp16(uint32_t s, const void* g) {
    asm volatile("cp.async.cg.shared.global [%0], [%1], 16;" :: "r"(s), "l"(g) : "memory");
}
__device__ __forceinline__ void cp_commit() {
    asm volatile("cp.async.commit_group;" ::: "memory");
}
__device__ __forceinline__ void cp_wait2() {
    asm volatile("cp.async.wait_group 2;" ::: "memory");
}
__device__ __forceinline__ void ldmx4(uint32_t* r, uint32_t a) {
    asm volatile("ldmatrix.sync.aligned.m8n8.x4.shared.b16 {%0,%1,%2,%3}, [%4];"
                 : "=r"(r[0]), "=r"(r[1]), "=r"(r[2]), "=r"(r[3]) : "r"(a));
}
__device__ __forceinline__ void hmma(float* c, const uint32_t* a, const uint32_t* b) {
    asm volatile(
        "mma.sync.aligned.m16n8k16.row.col.f32.bf16.bf16.f32 "
        "{%0,%1,%2,%3}, {%4,%5,%6,%7}, {%8,%9}, {%0,%1,%2,%3};"
        : "+f"(c[0]), "+f"(c[1]), "+f"(c[2]), "+f"(c[3])
        : "r"(a[0]), "r"(a[1]), "r"(a[2]), "r"(a[3]), "r"(b[0]), "r"(b[1]));
}

// split 4 fp32 -> packed bf16x2 hi pair + lo pair (RN split)
__device__ __forceinline__ void split4(float4 f, uint2& hi, uint2& lo) {
    __nv_bfloat16 h0 = __float2bfloat16(f.x), h1 = __float2bfloat16(f.y);
    __nv_bfloat16 h2 = __float2bfloat16(f.z), h3 = __float2bfloat16(f.w);
    __nv_bfloat162 H01 = __halves2bfloat162(h0, h1);
    __nv_bfloat162 H23 = __halves2bfloat162(h2, h3);
    __nv_bfloat162 L01 = __halves2bfloat162(
        __float2bfloat16(f.x - __bfloat162float(h0)),
        __float2bfloat16(f.y - __bfloat162float(h1)));
    __nv_bfloat162 L23 = __halves2bfloat162(
        __float2bfloat16(f.z - __bfloat162float(h2)),
        __float2bfloat16(f.w - __bfloat162float(h3)));
    hi.x = *(uint32_t*)&H01; hi.y = *(uint32_t*)&H23;
    lo.x = *(uint32_t*)&L01; lo.y = *(uint32_t*)&L23;
}

// ================= fused bf16-split HMMA GEMM ===============================
// MODE==3: A fp32 in gmem; producer LDGs fp32, splits to (Ah, Al) bf16 in smem
//          (R5-proven ordering); C = Ah*Bh^T + Ah*Bl^T + Al*Bh^T.
// MODE==2: A exact bf16 in gmem (spikes); C = A*Bh^T + A*Bl^T.
// B pre-split bf16 via cp.async. CTA tile BM x 128, BK=32, 256 threads,
// 4-stage pipeline, prefetch distance 3, wait_group 2.
// blockIdx.z = K split; partial to C + z*M*Ntot.
#define BKT 32
#define NSTG 4

template<int MODE, int BM>
__global__ void __launch_bounds__(256, 2)
hmma_fused(const void* __restrict__ Araw,
           const __nv_bfloat16* __restrict__ Bh, const __nv_bfloat16* __restrict__ Bl,
           int kChunk, int lda, int Ntot, float* __restrict__ C, int M)
{
    extern __shared__ __nv_bfloat16 dsm[];
    constexpr int TILE_A = BM * BKT;
    constexpr int TILE_B = 128 * BKT;
    constexpr int NTA    = (MODE == 3) ? 2 : 1;            // Ah,(Al)
    constexpr int STG    = NTA * TILE_A + 2 * TILE_B;
    constexpr int OFF_AL = TILE_A;
    constexpr int OFF_BH = NTA * TILE_A;
    constexpr int OFF_BL = OFF_BH + TILE_B;

    constexpr int WM   = BM / 32;        // M warp groups (2 for BM=64)
    constexpr int NCOL = 128 / (8 / WM); // cols per warp
    constexpr int NJ   = NCOL / 8;
    constexpr int NP   = NCOL / 16;
    constexpr int AIT  = BM / 32;        // fp32 float4 loads per thread

    const int tid  = threadIdx.x;
    const int wid  = tid >> 5;
    const int lane = tid & 31;
    const int wm   = wid & (WM - 1);
    const int wn   = wid / WM;

    const int rowBase = blockIdx.y * BM;
    const int colBase = blockIdx.x * 128;
    const int kOff    = blockIdx.z * kChunk;
    const int NT      = kChunk / BKT;

    const uint32_t smemB = s2u(dsm);
    const float* A32        = (const float*)Araw;
    const __nv_bfloat16* A16 = (const __nv_bfloat16*)Araw;

    float acc[2][NJ][4];
#pragma unroll
    for (int mi = 0; mi < 2; mi++)
#pragma unroll
        for (int nj = 0; nj < NJ; nj++)
#pragma unroll
            for (int q = 0; q < 4; q++) acc[mi][nj][q] = 0.f;

    // ---- B producer (cp.async, bf16 hi+lo; B always 128 rows) ----
    auto issueB = [&](int kt) {
        const int s  = kt % NSTG;
        const int kl = kt * BKT + kOff;
        const uint32_t base = smemB + (uint32_t)(s * STG) * 2;
#pragma unroll
        for (int i = 0; i < 2; i++) {
            const int v = tid + i * 256;
            const int m = v >> 2, u = v & 3;
            const uint32_t so = (uint32_t)(m * 64 + ((u ^ ((m >> 1) & 3)) << 4));
            const size_t gb = (size_t)(colBase + m) * lda + kl + u * 8;
            cp16(base + OFF_BH * 2 + so, Bh + gb);
            cp16(base + OFF_BL * 2 + so, Bl + gb);
        }
    };
    // ---- A producer, MODE2: exact bf16 via cp.async ----
    auto issueA2 = [&](int kt) {
        const int s  = kt % NSTG;
        const int kl = kt * BKT + kOff;
        const uint32_t base = smemB + (uint32_t)(s * STG) * 2;
#pragma unroll
        for (int i = 0; i < ((BM >= 64) ? BM / 64 : 1); i++) {
            const int v = tid + i * 256;
            const int m = v >> 2, u = v & 3;
            if (m < BM) {
                const uint32_t so = (uint32_t)(m * 64 + ((u ^ ((m >> 1) & 3)) << 4));
                cp16(base + so, A16 + (size_t)(rowBase + m) * lda + kl + u * 8);
            }
        }
    };
    // ---- A producer, MODE3: LDG fp32 into regs (R5 ordering) ----
    auto ldgA = [&](int kt, float4* f) {
#pragma unroll
        for (int i = 0; i < AIT; i++) {
            const int fv = tid + i * 256;
            const int row = fv >> 3, u4 = fv & 7;
            f[i] = *(const float4*)(A32 + (size_t)(rowBase + row) * lda
                                    + kt * BKT + kOff + u4 * 4);
        }
    };
    auto stsA = [&](int kt, const float4* f) {
        const int s = kt % NSTG;
        char* base = (char*)dsm + (size_t)(s * STG) * 2;
#pragma unroll
        for (int i = 0; i < AIT; i++) {
            const int fv = tid + i * 256;
            const int row = fv >> 3, u4 = fv & 7;
            const int u = u4 >> 1, half = u4 & 1;
            const uint32_t so = (uint32_t)(row * 64 + ((u ^ ((row >> 1) & 3)) << 4) + half * 8);
            uint2 hi, lo;
            split4(f[i], hi, lo);
            *(uint2*)(base + so)              = hi;
            *(uint2*)(base + OFF_AL * 2 + so) = lo;
        }
    };

    // ---- compute one BK=32 stage: all products ----
    auto compute = [&](int s) {
        const uint32_t base = smemB + (uint32_t)(s * STG) * 2;
#pragma unroll
        for (int k16 = 0; k16 < 2; k16++) {
            uint32_t ah[2][4], al[2][4];
#pragma unroll
            for (int mi = 0; mi < 2; mi++) {
                const int row = wm * 32 + mi * 16 + (lane & 15);
                const int u   = k16 * 2 + (lane >> 4);
                const uint32_t off = (uint32_t)(row * 64 + ((u ^ ((row >> 1) & 3)) << 4));
                ldmx4(ah[mi], base + off);
                if (MODE == 3) ldmx4(al[mi], base + OFF_AL * 2 + off);
            }
#pragma unroll
            for (int np = 0; np < NP; np++) {
                const int n = wn * NCOL + np * 16 + ((lane >> 4) << 3) + (lane & 7);
                const int u = k16 * 2 + ((lane >> 3) & 1);
                const uint32_t boff = (uint32_t)(n * 64 + ((u ^ ((n >> 1) & 3)) << 4));
                uint32_t bh[4], bl[4];
                ldmx4(bh, base + OFF_BH * 2 + boff);
                ldmx4(bl, base + OFF_BL * 2 + boff);
#pragma unroll
                for (int mi = 0; mi < 2; mi++) {
                    hmma(acc[mi][2 * np],     ah[mi], bh);
                    hmma(acc[mi][2 * np + 1], ah[mi], bh + 2);
                    hmma(acc[mi][2 * np],     ah[mi], bl);
                    hmma(acc[mi][2 * np + 1], ah[mi], bl + 2);
                    if (MODE == 3) {
                        hmma(acc[mi][2 * np],     al[mi], bh);
                        hmma(acc[mi][2 * np + 1], al[mi], bh + 2);
                    }
                }
            }
        }
    };

    // ---- prologue: fill stages 0,1,2 ----
    float4 f[AIT];
#pragma unroll
    for (int p = 0; p < NSTG - 1; p++) {
        if (p < NT) {
            if (MODE == 3) { ldgA(p, f); stsA(p, f); } else { issueA2(p); }
            issueB(p);
        }
        cp_commit();
    }
    cp_wait2();
    __syncthreads();

    // ---- mainloop: prefetch distance 3, wait_group 2 ----
    for (int kt = 0; kt < NT; kt++) {
        const bool pf = (kt + NSTG - 1 < NT);
        if (MODE == 3 && pf) ldgA(kt + NSTG - 1, f);   // LDG hidden under MMA
        if (pf) { if (MODE == 2) issueA2(kt + NSTG - 1); issueB(kt + NSTG - 1); }
        cp_commit();
        compute(kt % NSTG);
        if (MODE == 3 && pf) stsA(kt + NSTG - 1, f);   // convert + store after MMA
        cp_wait2();
        __syncthreads();
    }

    // ---- epilogue ----
    float* Cz = C + (size_t)blockIdx.z * M * Ntot;
#pragma unroll
    for (int mi = 0; mi < 2; mi++) {
        const int row = rowBase + wm * 32 + mi * 16 + (lane >> 2);
#pragma unroll
        for (int nj = 0; nj < NJ; nj++) {
            const int col = colBase + wn * NCOL + nj * 8 + (lane & 3) * 2;
            *(float2*)(Cz + (size_t)row * Ntot + col) =
                make_float2(acc[mi][nj][0], acc[mi][nj][1]);
            *(float2*)(Cz + (size_t)(row + 8) * Ntot + col) =
                make_float2(acc[mi][nj][2], acc[mi][nj][3]);
        }
    }
}

// =========================== small kernels ==================================
// one launch splits Wa, Wb, W1 into hi/lo
#define NWA (NF * NK / 4)
#define NW1 (NH * NF / 4)
__global__ void split_all(const float* __restrict__ Wa, const float* __restrict__ Wb,
                          const float* __restrict__ W1)
{
    const int i = blockIdx.x * blockDim.x + threadIdx.x;
    const float* src;
    __nv_bfloat16 *hi, *lo;
    int j = i;
    if (i < NWA)            { src = Wa; hi = g_Wah; lo = g_Wal; }
    else if (i < 2 * NWA)   { src = Wb; hi = g_Wbh; lo = g_Wbl; j = i - NWA; }
    else if (i < 2 * NWA + NW1) { src = W1; hi = g_W1h; lo = g_W1l; j = i - 2 * NWA; }
    else return;
    float4 v = ((const float4*)src)[j];
    uint2 h, l;
    split4(v, h, l);
    ((uint2*)hi)[j] = h;
    ((uint2*)lo)[j] = l;
}

// reduce basal split-K partials + precompute mb(t) recurrence in one pass
__global__ void reduce_basal_mb()
{
    const int i = blockIdx.x * blockDim.x + threadIdx.x;   // over NB*NF
    if (i >= NB * NF) return;
    float mb = 0.f;
#pragma unroll
    for (int t = 0; t < TSTEPS; t++) {
        const int e = t * NB * NF + i;
        float s = 0.f;
#pragma unroll
        for (int p = 0; p < KSB; p++) s += g_bpart[(size_t)p * (TSTEPS * NB * NF) + e];
        mb += (s - mb) * 0.5f;
        g_mball[e] = mb;
    }
}

// ---- mc_all: whole MC-neuron time recurrence, elementwise, ONE launch ------
// Sums the KSA apical partials (fixed order), runs recurrence in registers.
__global__ void mc_all()
{
    const int i = blockIdx.x * blockDim.x + threadIdx.x;   // over NBS*NF/4
    if (i >= NBS * NF / 4) return;
    const int e = i * 4;
    const int f = e & (NF - 1);
    const int b = e >> 14;                                 // e / (NS*NF)

    float4 mav = make_float4(0.f, 0.f, 0.f, 0.f);
    float4 msv = make_float4(0.f, 0.f, 0.f, 0.f);

#pragma unroll
    for (int t = 0; t < TSTEPS; t++) {
        float4 p0 = ((const float4*)(g_apical + (size_t)t * NBS * NF))[i];
        float4 p1 = ((const float4*)(g_apical + (size_t)(TSTEPS * NBS * NF)
                                     + (size_t)t * NBS * NF))[i];
        float4 ap = make_float4(p0.x + p1.x, p0.y + p1.y, p0.z + p1.z, p0.w + p1.w);
        float4 mbv = *(const float4*)(g_mball + t * NB * NF + b * NF + f);
        float4 spv;

        mav.x += (ap.x - mav.x) * 0.5f;
        msv.x += (mav.x + mbv.x - msv.x) * 0.5f;
        spv.x = (msv.x > 1.0f) ? 1.f : 0.f;  msv.x *= (1.f - spv.x);

        mav.y += (ap.y - mav.y) * 0.5f;
        msv.y += (mav.y + mbv.y - msv.y) * 0.5f;
        spv.y = (msv.y > 1.0f) ? 1.f : 0.f;  msv.y *= (1.f - spv.y);

        mav.z += (ap.z - mav.z) * 0.5f;
        msv.z += (mav.z + mbv.z - msv.z) * 0.5f;
        spv.z = (msv.z > 1.0f) ? 1.f : 0.f;  msv.z *= (1.f - spv.z);

        mav.w += (ap.w - mav.w) * 0.5f;
        msv.w += (mav.w + mbv.w - msv.w) * 0.5f;
        spv.w = (msv.w > 1.0f) ? 1.f : 0.f;  msv.w *= (1.f - spv.w);

        __nv_bfloat162* sp = (__nv_bfloat162*)(g_spall + (size_t)t * NBS * NF + e);
        sp[0] = __halves2bfloat162(__float2bfloat16(spv.x), __float2bfloat16(spv.y));
        sp[1] = __halves2bfloat162(__float2bfloat16(spv.z), __float2bfloat16(spv.w));
    }
}

// ---- lif_all: LIF recurrence (ml in regs) + readout + finalize, ONE launch -
__global__ void lif_all(const float* __restrict__ b1, const float* __restrict__ W2,
                        const float* __restrict__ b2, float* __restrict__ out)
{
    const int gw   = (blockIdx.x * blockDim.x + threadIdx.x) >> 5;  // row bs
    const int lane = threadIdx.x & 31;
    if (gw >= NBS) return;

    float ml[NH / 32];
#pragma unroll
    for (int j = 0; j < NH / 32; j++) ml[j] = 0.f;
    float a[NL];
#pragma unroll
    for (int l = 0; l < NL; l++) a[l] = 0.f;

    for (int t = 0; t < TSTEPS; t++) {
        const float* hrow = g_hall + ((size_t)t * NBS + gw) * NH;
#pragma unroll
        for (int j = 0; j < NH / 32; j++) {
            const int k = j * 32 + lane;
            const float h = b1[k] + hrow[k];
            float m = ml[j];
            m += (h - m) * 0.5f;
            const float s = (m > 0.5f) ? 1.f : 0.f;
            ml[j] = m * (1.f - s);
            if (s != 0.f) {
#pragma unroll
                for (int l = 0; l < NL; l++) a[l] += W2[l * NH + k];
            }
        }
    }
#pragma unroll
    for (int l = 0; l < NL; l++) {
#pragma unroll
        for (int o = 16; o; o >>= 1) a[l] += __shfl_xor_sync(0xffffffffu, a[l], o);
    }
    if (lane == 0) {
        const int b = gw >> 5;          // / NS
        const int sdx = gw & 31;        // % NS
#pragma unroll
        for (int l = 0; l < NL; l++)
            out[b * NL * NS + l * NS + sdx] = a[l] * (1.f / TSTEPS) + b2[l];
    }
}

// ---------------------------------------------------------------------------
extern "C" void kernel_launch(void* const* d_in, const int* in_sizes, int n_in,
                              void* d_out, int out_size)
{
    (void)in_sizes; (void)n_in; (void)out_size;
    const float* se = (const float*)d_in[0];
    const float* te = (const float*)d_in[1];
    const float* Wb = (const float*)d_in[2];
    const float* Wa = (const float*)d_in[3];
    const float* W1 = (const float*)d_in[4];
    const float* b1 = (const float*)d_in[5];
    const float* W2 = (const float*)d_in[6];
    const float* b2 = (const float*)d_in[7];
    float* out = (float*)d_out;

    float *apical, *bpart, *hall;
    __nv_bfloat16 *Wah, *Wal, *W1h, *W1l, *spall;
    __nv_bfloat16 *Wbh, *Wbl;
    cudaGetSymbolAddress((void**)&apical, g_apical);
    cudaGetSymbolAddress((void**)&bpart,  g_bpart);
    cudaGetSymbolAddress((void**)&hall,   g_hall);
    cudaGetSymbolAddress((void**)&Wah,    g_Wah);
    cudaGetSymbolAddress((void**)&Wal,    g_Wal);
    cudaGetSymbolAddress((void**)&Wbh,    g_Wbh);
    cudaGetSymbolAddress((void**)&Wbl,    g_Wbl);
    cudaGetSymbolAddress((void**)&W1h,    g_W1h);
    cudaGetSymbolAddress((void**)&W1l,    g_W1l);
    cudaGetSymbolAddress((void**)&spall,  g_spall);

    // smem: MODE3/BM64 stage = (2*64*32 + 2*128*32)*2B = 24KB; x4 = 98304
    //       MODE2/BM64 stage  = (64*32 + 2*128*32)*2B  = 20KB; x4 = 81920
    const int SMEM_M3 = (2 * 64 * BKT + 2 * 128 * BKT) * 2 * NSTG;   // 98304
    const int SMEM_M2 = (64 * BKT + 2 * 128 * BKT) * 2 * NSTG;       // 81920
    cudaFuncSetAttribute((const void*)hmma_fused<3, 64>,
                         cudaFuncAttributeMaxDynamicSharedMemorySize, SMEM_M3);
    cudaFuncSetAttribute((const void*)hmma_fused<2, 64>,
                         cudaFuncAttributeMaxDynamicSharedMemorySize, SMEM_M2);

    // weight hi/lo splits (one launch; te/se split in-kernel)
    split_all<<<(2 * NWA + NW1 + 255) / 256, 256>>>(Wa, Wb, W1);

    // basal: fp32-A fused-split HMMA BM=64, split-K=7
    hmma_fused<3, 64><<<dim3(NF / 128, (TSTEPS * NB) / 64, KSB), 256, SMEM_M3>>>(
        se, Wbh, Wbl, KCH_B, NK, NF, bpart, TSTEPS * NB);
    reduce_basal_mb<<<(NB * NF + 255) / 256, 256>>>();

    // apical: fp32-A fused-split HMMA BM=64, split-K=2 (2048 CTAs ~7 waves)
    hmma_fused<3, 64><<<dim3(NF / 128, (TSTEPS * NBS) / 64, KSA), 256, SMEM_M3>>>(
        te, Wah, Wal, KCH_A, NK, NF, apical, TSTEPS * NBS);

    // MC neuron: sum apical partials + all 8 steps in one elementwise pass
    mc_all<<<(NBS * NF / 4 + 255) / 256, 256>>>();

    // h for ALL steps: one batched GEMM, M=16384 K=512 N=512 (2 products)
    hmma_fused<2, 64><<<dim3(NH / 128, (TSTEPS * NBS) / 64, 1), 256, SMEM_M2>>>(
        spall, W1h, W1l, NF, NF, NH, hall, TSTEPS * NBS);

    // LIF + readout + finalize: one launch, ml in registers
    lif_all<<<(NBS * 32 + 255) / 256, 256>>>(b1, W2, b2, out);
}

// round 11
// speedup vs baseline: 1.0123x; 1.0123x over previous
#include <cuda_runtime.h>
#include <cuda_bf16.h>
#include <cstdint>

// Problem constants
#define TSTEPS 8
#define NB 64
#define NS 32
#define NBS 2048          // B*S
#define NK 3136           // DS == DT
#define NF 512
#define NH 512
#define NL 18
#define KSB 7             // split-K for basal GEMM
#define KCH_B 448         // 3136 / 7 (multiple of 32)

// ---------------- scratch (__device__ globals; no allocation allowed) -------
__device__ float g_apical[TSTEPS * NBS * NF];        // 33.5 MB
__device__ float g_bpart[KSB * TSTEPS * NB * NF];
__device__ float g_mball[TSTEPS * NB * NF];          // precomputed mb(t)
__device__ __align__(16) __nv_bfloat16 g_spall[TSTEPS * NBS * NF];  // all spikes
__device__ float g_hall[TSTEPS * NBS * NH];          // 67 MB
// bf16 hi/lo splits (weights only)
__device__ __align__(16) __nv_bfloat16 g_Wah[NF * NK];
__device__ __align__(16) __nv_bfloat16 g_Wal[NF * NK];
__device__ __align__(16) __nv_bfloat16 g_Wbh[NF * NK];
__device__ __align__(16) __nv_bfloat16 g_Wbl[NF * NK];
__device__ __align__(16) __nv_bfloat16 g_W1h[NH * NF];
__device__ __align__(16) __nv_bfloat16 g_W1l[NH * NF];

// ============================ PTX helpers ==================================
__device__ __forceinline__ uint32_t s2u(const void* p) {
    uint32_t a;
    asm("{ .reg .u64 t; cvta.to.shared.u64 t, %1; cvt.u32.u64 %0, t; }"
        : "=r"(a) : "l"(p));
    return a;
}
__device__ __forceinline__ void cp16(uint32_t s, const void* g) {
    asm volatile("cp.async.cg.shared.global [%0], [%1], 16;" :: "r"(s), "l"(g) : "memory");
}
__device__ __forceinline__ void cp_commit() {
    asm volatile("cp.async.commit_group;" ::: "memory");
}
__device__ __forceinline__ void cp_wait2() {
    asm volatile("cp.async.wait_group 2;" ::: "memory");
}
__device__ __forceinline__ void ldmx4(uint32_t* r, uint32_t a) {
    asm volatile("ldmatrix.sync.aligned.m8n8.x4.shared.b16 {%0,%1,%2,%3}, [%4];"
                 : "=r"(r[0]), "=r"(r[1]), "=r"(r[2]), "=r"(r[3]) : "r"(a));
}
__device__ __forceinline__ void hmma(float* c, const uint32_t* a, const uint32_t* b) {
    asm volatile(
        "mma.sync.aligned.m16n8k16.row.col.f32.bf16.bf16.f32 "
        "{%0,%1,%2,%3}, {%4,%5,%6,%7}, {%8,%9}, {%0,%1,%2,%3};"
        : "+f"(c[0]), "+f"(c[1]), "+f"(c[2]), "+f"(c[3])
        : "r"(a[0]), "r"(a[1]), "r"(a[2]), "r"(a[3]), "r"(b[0]), "r"(b[1]));
}

// split 4 fp32 -> packed bf16x2 hi pair + lo pair (RN split)
__device__ __forceinline__ void split4(float4 f, uint2& hi, uint2& lo) {
    __nv_bfloat16 h0 = __float2bfloat16(f.x), h1 = __float2bfloat16(f.y);
    __nv_bfloat16 h2 = __float2bfloat16(f.z), h3 = __float2bfloat16(f.w);
    __nv_bfloat162 H01 = __halves2bfloat162(h0, h1);
    __nv_bfloat162 H23 = __halves2bfloat162(h2, h3);
    __nv_bfloat162 L01 = __halves2bfloat162(
        __float2bfloat16(f.x - __bfloat162float(h0)),
        __float2bfloat16(f.y - __bfloat162float(h1)));
    __nv_bfloat162 L23 = __halves2bfloat162(
        __float2bfloat16(f.z - __bfloat162float(h2)),
        __float2bfloat16(f.w - __bfloat162float(h3)));
    hi.x = *(uint32_t*)&H01; hi.y = *(uint32_t*)&H23;
    lo.x = *(uint32_t*)&L01; lo.y = *(uint32_t*)&L23;
}

// ================= fused bf16-split HMMA GEMM ===============================
// MODE==3: A fp32 in gmem; producer LDGs fp32, splits to (Ah, Al) bf16 in smem
//          (R5-proven ordering); C = Ah*Bh^T + Ah*Bl^T + Al*Bh^T.
// MODE==2: A exact bf16 in gmem (spikes); C = A*Bh^T + A*Bl^T.
// B pre-split bf16 via cp.async. CTA tile BM x 128, BK=32, 256 threads,
// 4-stage pipeline, prefetch distance 3, wait_group 2.
// HMMA issue is grouped per-product (hh wave, hl wave, lh wave) so RAW-
// dependent MMAs on the same accumulator are >=4 apart; per-accumulator
// accumulation order (hh, hl, lh) is unchanged => bitwise-identical result.
#define BKT 32
#define NSTG 4

template<int MODE, int BM>
__global__ void __launch_bounds__(256, 2)
hmma_fused(const void* __restrict__ Araw,
           const __nv_bfloat16* __restrict__ Bh, const __nv_bfloat16* __restrict__ Bl,
           int kChunk, int lda, int Ntot, float* __restrict__ C, int M)
{
    extern __shared__ __nv_bfloat16 dsm[];
    constexpr int TILE_A = BM * BKT;
    constexpr int TILE_B = 128 * BKT;
    constexpr int NTA    = (MODE == 3) ? 2 : 1;            // Ah,(Al)
    constexpr int STG    = NTA * TILE_A + 2 * TILE_B;
    constexpr int OFF_AL = TILE_A;
    constexpr int OFF_BH = NTA * TILE_A;
    constexpr int OFF_BL = OFF_BH + TILE_B;

    constexpr int WM   = BM / 32;        // M warp groups (2 for BM=64)
    constexpr int NCOL = 128 / (8 / WM); // cols per warp
    constexpr int NJ   = NCOL / 8;
    constexpr int NP   = NCOL / 16;
    constexpr int AIT  = BM / 32;        // fp32 float4 loads per thread

    const int tid  = threadIdx.x;
    const int wid  = tid >> 5;
    const int lane = tid & 31;
    const int wm   = wid & (WM - 1);
    const int wn   = wid / WM;

    const int rowBase = blockIdx.y * BM;
    const int colBase = blockIdx.x * 128;
    const int kOff    = blockIdx.z * kChunk;
    const int NT      = kChunk / BKT;

    const uint32_t smemB = s2u(dsm);
    const float* A32        = (const float*)Araw;
    const __nv_bfloat16* A16 = (const __nv_bfloat16*)Araw;

    float acc[2][NJ][4];
#pragma unroll
    for (int mi = 0; mi < 2; mi++)
#pragma unroll
        for (int nj = 0; nj < NJ; nj++)
#pragma unroll
            for (int q = 0; q < 4; q++) acc[mi][nj][q] = 0.f;

    // ---- B producer (cp.async, bf16 hi+lo; B always 128 rows) ----
    auto issueB = [&](int kt) {
        const int s  = kt % NSTG;
        const int kl = kt * BKT + kOff;
        const uint32_t base = smemB + (uint32_t)(s * STG) * 2;
#pragma unroll
        for (int i = 0; i < 2; i++) {
            const int v = tid + i * 256;
            const int m = v >> 2, u = v & 3;
            const uint32_t so = (uint32_t)(m * 64 + ((u ^ ((m >> 1) & 3)) << 4));
            const size_t gb = (size_t)(colBase + m) * lda + kl + u * 8;
            cp16(base + OFF_BH * 2 + so, Bh + gb);
            cp16(base + OFF_BL * 2 + so, Bl + gb);
        }
    };
    // ---- A producer, MODE2: exact bf16 via cp.async ----
    auto issueA2 = [&](int kt) {
        const int s  = kt % NSTG;
        const int kl = kt * BKT + kOff;
        const uint32_t base = smemB + (uint32_t)(s * STG) * 2;
#pragma unroll
        for (int i = 0; i < ((BM >= 64) ? BM / 64 : 1); i++) {
            const int v = tid + i * 256;
            const int m = v >> 2, u = v & 3;
            if (m < BM) {
                const uint32_t so = (uint32_t)(m * 64 + ((u ^ ((m >> 1) & 3)) << 4));
                cp16(base + so, A16 + (size_t)(rowBase + m) * lda + kl + u * 8);
            }
        }
    };
    // ---- A producer, MODE3: LDG fp32 into regs (R5 ordering) ----
    auto ldgA = [&](int kt, float4* f) {
#pragma unroll
        for (int i = 0; i < AIT; i++) {
            const int fv = tid + i * 256;
            const int row = fv >> 3, u4 = fv & 7;
            f[i] = *(const float4*)(A32 + (size_t)(rowBase + row) * lda
                                    + kt * BKT + kOff + u4 * 4);
        }
    };
    auto stsA = [&](int kt, const float4* f) {
        const int s = kt % NSTG;
        char* base = (char*)dsm + (size_t)(s * STG) * 2;
#pragma unroll
        for (int i = 0; i < AIT; i++) {
            const int fv = tid + i * 256;
            const int row = fv >> 3, u4 = fv & 7;
            const int u = u4 >> 1, half = u4 & 1;
            const uint32_t so = (uint32_t)(row * 64 + ((u ^ ((row >> 1) & 3)) << 4) + half * 8);
            uint2 hi, lo;
            split4(f[i], hi, lo);
            *(uint2*)(base + so)              = hi;
            *(uint2*)(base + OFF_AL * 2 + so) = lo;
        }
    };

    // ---- compute one BK=32 stage: product-wave ordering ----
    auto compute = [&](int s) {
        const uint32_t base = smemB + (uint32_t)(s * STG) * 2;
#pragma unroll
        for (int k16 = 0; k16 < 2; k16++) {
            uint32_t ah[2][4], al[2][4];
#pragma unroll
            for (int mi = 0; mi < 2; mi++) {
                const int row = wm * 32 + mi * 16 + (lane & 15);
                const int u   = k16 * 2 + (lane >> 4);
                const uint32_t off = (uint32_t)(row * 64 + ((u ^ ((row >> 1) & 3)) << 4));
                ldmx4(ah[mi], base + off);
                if (MODE == 3) ldmx4(al[mi], base + OFF_AL * 2 + off);
            }
#pragma unroll
            for (int np = 0; np < NP; np++) {
                const int n = wn * NCOL + np * 16 + ((lane >> 4) << 3) + (lane & 7);
                const int u = k16 * 2 + ((lane >> 3) & 1);
                const uint32_t boff = (uint32_t)(n * 64 + ((u ^ ((n >> 1) & 3)) << 4));
                uint32_t bh[4], bl[4];
                ldmx4(bh, base + OFF_BH * 2 + boff);
                ldmx4(bl, base + OFF_BL * 2 + boff);
                // wave 1: hh for all 4 accumulators (independent)
                hmma(acc[0][2 * np],     ah[0], bh);
                hmma(acc[0][2 * np + 1], ah[0], bh + 2);
                hmma(acc[1][2 * np],     ah[1], bh);
                hmma(acc[1][2 * np + 1], ah[1], bh + 2);
                // wave 2: hl (dep distance 4 from wave 1)
                hmma(acc[0][2 * np],     ah[0], bl);
                hmma(acc[0][2 * np + 1], ah[0], bl + 2);
                hmma(acc[1][2 * np],     ah[1], bl);
                hmma(acc[1][2 * np + 1], ah[1], bl + 2);
                // wave 3: lh (MODE3 only)
                if (MODE == 3) {
                    hmma(acc[0][2 * np],     al[0], bh);
                    hmma(acc[0][2 * np + 1], al[0], bh + 2);
                    hmma(acc[1][2 * np],     al[1], bh);
                    hmma(acc[1][2 * np + 1], al[1], bh + 2);
                }
            }
        }
    };

    // ---- prologue: fill stages 0,1,2 ----
    float4 f[AIT];
#pragma unroll
    for (int p = 0; p < NSTG - 1; p++) {
        if (p < NT) {
            if (MODE == 3) { ldgA(p, f); stsA(p, f); } else { issueA2(p); }
            issueB(p);
        }
        cp_commit();
    }
    cp_wait2();
    __syncthreads();

    // ---- mainloop: prefetch distance 3, wait_group 2 ----
    for (int kt = 0; kt < NT; kt++) {
        const bool pf = (kt + NSTG - 1 < NT);
        if (MODE == 3 && pf) ldgA(kt + NSTG - 1, f);   // LDG hidden under MMA
        if (pf) { if (MODE == 2) issueA2(kt + NSTG - 1); issueB(kt + NSTG - 1); }
        cp_commit();
        compute(kt % NSTG);
        if (MODE == 3 && pf) stsA(kt + NSTG - 1, f);   // convert + store after MMA
        cp_wait2();
        __syncthreads();
    }

    // ---- epilogue ----
    float* Cz = C + (size_t)blockIdx.z * M * Ntot;
#pragma unroll
    for (int mi = 0; mi < 2; mi++) {
        const int row = rowBase + wm * 32 + mi * 16 + (lane >> 2);
#pragma unroll
        for (int nj = 0; nj < NJ; nj++) {
            const int col = colBase + wn * NCOL + nj * 8 + (lane & 3) * 2;
            *(float2*)(Cz + (size_t)row * Ntot + col) =
                make_float2(acc[mi][nj][0], acc[mi][nj][1]);
            *(float2*)(Cz + (size_t)(row + 8) * Ntot + col) =
                make_float2(acc[mi][nj][2], acc[mi][nj][3]);
        }
    }
}

// =========================== small kernels ==================================
// one launch splits Wa, Wb, W1 into hi/lo
#define NWA (NF * NK / 4)
#define NW1 (NH * NF / 4)
__global__ void split_all(const float* __restrict__ Wa, const float* __restrict__ Wb,
                          const float* __restrict__ W1)
{
    const int i = blockIdx.x * blockDim.x + threadIdx.x;
    const float* src;
    __nv_bfloat16 *hi, *lo;
    int j = i;
    if (i < NWA)            { src = Wa; hi = g_Wah; lo = g_Wal; }
    else if (i < 2 * NWA)   { src = Wb; hi = g_Wbh; lo = g_Wbl; j = i - NWA; }
    else if (i < 2 * NWA + NW1) { src = W1; hi = g_W1h; lo = g_W1l; j = i - 2 * NWA; }
    else return;
    float4 v = ((const float4*)src)[j];
    uint2 h, l;
    split4(v, h, l);
    ((uint2*)hi)[j] = h;
    ((uint2*)lo)[j] = l;
}

// reduce basal split-K partials + precompute mb(t) recurrence in one pass
__global__ void reduce_basal_mb()
{
    const int i = blockIdx.x * blockDim.x + threadIdx.x;   // over NB*NF
    if (i >= NB * NF) return;
    float mb = 0.f;
#pragma unroll
    for (int t = 0; t < TSTEPS; t++) {
        const int e = t * NB * NF + i;
        float s = 0.f;
#pragma unroll
        for (int p = 0; p < KSB; p++) s += g_bpart[(size_t)p * (TSTEPS * NB * NF) + e];
        mb += (s - mb) * 0.5f;
        g_mball[e] = mb;
    }
}

// ---- mc_all: whole MC-neuron time recurrence, elementwise, ONE launch ------
__global__ void mc_all()
{
    const int i = blockIdx.x * blockDim.x + threadIdx.x;   // over NBS*NF/4
    if (i >= NBS * NF / 4) return;
    const int e = i * 4;
    const int f = e & (NF - 1);
    const int b = e >> 14;                                 // e / (NS*NF)

    float4 mav = make_float4(0.f, 0.f, 0.f, 0.f);
    float4 msv = make_float4(0.f, 0.f, 0.f, 0.f);

#pragma unroll
    for (int t = 0; t < TSTEPS; t++) {
        float4 ap  = ((const float4*)(g_apical + (size_t)t * NBS * NF))[i];
        float4 mbv = *(const float4*)(g_mball + t * NB * NF + b * NF + f);
        float4 spv;

        mav.x += (ap.x - mav.x) * 0.5f;
        msv.x += (mav.x + mbv.x - msv.x) * 0.5f;
        spv.x = (msv.x > 1.0f) ? 1.f : 0.f;  msv.x *= (1.f - spv.x);

        mav.y += (ap.y - mav.y) * 0.5f;
        msv.y += (mav.y + mbv.y - msv.y) * 0.5f;
        spv.y = (msv.y > 1.0f) ? 1.f : 0.f;  msv.y *= (1.f - spv.y);

        mav.z += (ap.z - mav.z) * 0.5f;
        msv.z += (mav.z + mbv.z - msv.z) * 0.5f;
        spv.z = (msv.z > 1.0f) ? 1.f : 0.f;  msv.z *= (1.f - spv.z);

        mav.w += (ap.w - mav.w) * 0.5f;
        msv.w += (mav.w + mbv.w - msv.w) * 0.5f;
        spv.w = (msv.w > 1.0f) ? 1.f : 0.f;  msv.w *= (1.f - spv.w);

        __nv_bfloat162* sp = (__nv_bfloat162*)(g_spall + (size_t)t * NBS * NF + e);
        sp[0] = __halves2bfloat162(__float2bfloat16(spv.x), __float2bfloat16(spv.y));
        sp[1] = __halves2bfloat162(__float2bfloat16(spv.z), __float2bfloat16(spv.w));
    }
}

// ---- lif_all: LIF recurrence (ml in regs) + readout + finalize, ONE launch -
__global__ void lif_all(const float* __restrict__ b1, const float* __restrict__ W2,
                        const float* __restrict__ b2, float* __restrict__ out)
{
    const int gw   = (blockIdx.x * blockDim.x + threadIdx.x) >> 5;  // row bs
    const int lane = threadIdx.x & 31;
    if (gw >= NBS) return;

    float ml[NH / 32];
#pragma unroll
    for (int j = 0; j < NH / 32; j++) ml[j] = 0.f;
    float a[NL];
#pragma unroll
    for (int l = 0; l < NL; l++) a[l] = 0.f;

    for (int t = 0; t < TSTEPS; t++) {
        const float* hrow = g_hall + ((size_t)t * NBS + gw) * NH;
#pragma unroll
        for (int j = 0; j < NH / 32; j++) {
            const int k = j * 32 + lane;
            const float h = b1[k] + hrow[k];
            float m = ml[j];
            m += (h - m) * 0.5f;
            const float s = (m > 0.5f) ? 1.f : 0.f;
            ml[j] = m * (1.f - s);
            if (s != 0.f) {
#pragma unroll
                for (int l = 0; l < NL; l++) a[l] += W2[l * NH + k];
            }
        }
    }
#pragma unroll
    for (int l = 0; l < NL; l++) {
#pragma unroll
        for (int o = 16; o; o >>= 1) a[l] += __shfl_xor_sync(0xffffffffu, a[l], o);
    }
    if (lane == 0) {
        const int b = gw >> 5;          // / NS
        const int sdx = gw & 31;        // % NS
#pragma unroll
        for (int l = 0; l < NL; l++)
            out[b * NL * NS + l * NS + sdx] = a[l] * (1.f / TSTEPS) + b2[l];
    }
}

// ---------------------------------------------------------------------------
extern "C" void kernel_launch(void* const* d_in, const int* in_sizes, int n_in,
                              void* d_out, int out_size)
{
    (void)in_sizes; (void)n_in; (void)out_size;
    const float* se = (const float*)d_in[0];
    const float* te = (const float*)d_in[1];
    const float* Wb = (const float*)d_in[2];
    const float* Wa = (const float*)d_in[3];
    const float* W1 = (const float*)d_in[4];
    const float* b1 = (const float*)d_in[5];
    const float* W2 = (const float*)d_in[6];
    const float* b2 = (const float*)d_in[7];
    float* out = (float*)d_out;

    float *apical, *bpart, *hall;
    __nv_bfloat16 *Wah, *Wal, *Wbh, *Wbl, *W1h, *W1l, *spall;
    cudaGetSymbolAddress((void**)&apical, g_apical);
    cudaGetSymbolAddress((void**)&bpart,  g_bpart);
    cudaGetSymbolAddress((void**)&hall,   g_hall);
    cudaGetSymbolAddress((void**)&Wah,    g_Wah);
    cudaGetSymbolAddress((void**)&Wal,    g_Wal);
    cudaGetSymbolAddress((void**)&Wbh,    g_Wbh);
    cudaGetSymbolAddress((void**)&Wbl,    g_Wbl);
    cudaGetSymbolAddress((void**)&W1h,    g_W1h);
    cudaGetSymbolAddress((void**)&W1l,    g_W1l);
    cudaGetSymbolAddress((void**)&spall,  g_spall);

    // smem: MODE3/BM64 stage = (2*64*32 + 2*128*32)*2B = 24KB; x4 = 98304
    //       MODE2/BM64 stage  = (64*32 + 2*128*32)*2B  = 20KB; x4 = 81920
    const int SMEM_M3 = (2 * 64 * BKT + 2 * 128 * BKT) * 2 * NSTG;   // 98304
    const int SMEM_M2 = (64 * BKT + 2 * 128 * BKT) * 2 * NSTG;       // 81920
    cudaFuncSetAttribute((const void*)hmma_fused<3, 64>,
                         cudaFuncAttributeMaxDynamicSharedMemorySize, SMEM_M3);
    cudaFuncSetAttribute((const void*)hmma_fused<2, 64>,
                         cudaFuncAttributeMaxDynamicSharedMemorySize, SMEM_M2);

    // weight hi/lo splits (one launch; te/se split in-kernel)
    split_all<<<(2 * NWA + NW1 + 255) / 256, 256>>>(Wa, Wb, W1);

    // basal: fp32-A fused-split HMMA BM=64, split-K=7
    hmma_fused<3, 64><<<dim3(NF / 128, (TSTEPS * NB) / 64, KSB), 256, SMEM_M3>>>(
        se, Wbh, Wbl, KCH_B, NK, NF, bpart, TSTEPS * NB);
    reduce_basal_mb<<<(NB * NF + 255) / 256, 256>>>();

    // apical: fp32-A fused-split HMMA BM=64, M=16384 N=512 K=3136 (no split-K)
    hmma_fused<3, 64><<<dim3(NF / 128, (TSTEPS * NBS) / 64, 1), 256, SMEM_M3>>>(
        te, Wah, Wal, NK, NK, NF, apical, TSTEPS * NBS);

    // MC neuron: all 8 steps in one elementwise pass (state in registers)
    mc_all<<<(NBS * NF / 4 + 255) / 256, 256>>>();

    // h for ALL steps: one batched GEMM, M=16384 K=512 N=512 (2 products)
    hmma_fused<2, 64><<<dim3(NH / 128, (TSTEPS * NBS) / 64, 1), 256, SMEM_M2>>>(
        spall, W1h, W1l, NF, NF, NH, hall, TSTEPS * NBS);

    // LIF + readout + finalize: one launch, ml in registers
    lif_all<<<(NBS * 32 + 255) / 256, 256>>>(b1, W2, b2, out);
}

// round 12
// speedup vs baseline: 1.0449x; 1.0323x over previous
#include <cuda_runtime.h>
#include <cuda_bf16.h>
#include <cstdint>

// Problem constants
#define TSTEPS 8
#define NB 64
#define NS 32
#define NBS 2048          // B*S
#define NK 3136           // DS == DT
#define NF 512
#define NH 512
#define NL 18
#define KSB 7             // split-K for basal GEMM
#define KCH_B 448         // 3136 / 7 (multiple of 32)

// ---------------- scratch (__device__ globals; no allocation allowed) -------
__device__ float g_bpart[KSB * TSTEPS * NB * NF];
__device__ float g_mball[TSTEPS * NB * NF];          // precomputed mb(t)
__device__ __align__(16) __nv_bfloat16 g_spall[NBS * TSTEPS * NF];  // (bs,t) rows
__device__ float g_opart[4 * NBS * NL];              // readout partials by k-chunk
// bf16 hi/lo splits (weights only)
__device__ __align__(16) __nv_bfloat16 g_Wah[NF * NK];
__device__ __align__(16) __nv_bfloat16 g_Wal[NF * NK];
__device__ __align__(16) __nv_bfloat16 g_Wbh[NF * NK];
__device__ __align__(16) __nv_bfloat16 g_Wbl[NF * NK];
__device__ __align__(16) __nv_bfloat16 g_W1h[NH * NF];
__device__ __align__(16) __nv_bfloat16 g_W1l[NH * NF];

// ============================ PTX helpers ==================================
__device__ __forceinline__ uint32_t s2u(const void* p) {
    uint32_t a;
    asm("{ .reg .u64 t; cvta.to.shared.u64 t, %1; cvt.u32.u64 %0, t; }"
        : "=r"(a) : "l"(p));
    return a;
}
__device__ __forceinline__ void cp16(uint32_t s, const void* g) {
    asm volatile("cp.async.cg.shared.global [%0], [%1], 16;" :: "r"(s), "l"(g) : "memory");
}
__device__ __forceinline__ void cp_commit() {
    asm volatile("cp.async.commit_group;" ::: "memory");
}
__device__ __forceinline__ void cp_wait2() {
    asm volatile("cp.async.wait_group 2;" ::: "memory");
}
__device__ __forceinline__ void ldmx4(uint32_t* r, uint32_t a) {
    asm volatile("ldmatrix.sync.aligned.m8n8.x4.shared.b16 {%0,%1,%2,%3}, [%4];"
                 : "=r"(r[0]), "=r"(r[1]), "=r"(r[2]), "=r"(r[3]) : "r"(a));
}
__device__ __forceinline__ void hmma(float* c, const uint32_t* a, const uint32_t* b) {
    asm volatile(
        "mma.sync.aligned.m16n8k16.row.col.f32.bf16.bf16.f32 "
        "{%0,%1,%2,%3}, {%4,%5,%6,%7}, {%8,%9}, {%0,%1,%2,%3};"
        : "+f"(c[0]), "+f"(c[1]), "+f"(c[2]), "+f"(c[3])
        : "r"(a[0]), "r"(a[1]), "r"(a[2]), "r"(a[3]), "r"(b[0]), "r"(b[1]));
}

// split 4 fp32 -> packed bf16x2 hi pair + lo pair (RN split)
__device__ __forceinline__ void split4(float4 f, uint2& hi, uint2& lo) {
    __nv_bfloat16 h0 = __float2bfloat16(f.x), h1 = __float2bfloat16(f.y);
    __nv_bfloat16 h2 = __float2bfloat16(f.z), h3 = __float2bfloat16(f.w);
    __nv_bfloat162 H01 = __halves2bfloat162(h0, h1);
    __nv_bfloat162 H23 = __halves2bfloat162(h2, h3);
    __nv_bfloat162 L01 = __halves2bfloat162(
        __float2bfloat16(f.x - __bfloat162float(h0)),
        __float2bfloat16(f.y - __bfloat162float(h1)));
    __nv_bfloat162 L23 = __halves2bfloat162(
        __float2bfloat16(f.z - __bfloat162float(h2)),
        __float2bfloat16(f.w - __bfloat162float(h3)));
    hi.x = *(uint32_t*)&H01; hi.y = *(uint32_t*)&H23;
    lo.x = *(uint32_t*)&L01; lo.y = *(uint32_t*)&L23;
}

// ================= fused bf16-split HMMA GEMM + fused consumers =============
// MODE==3: A fp32 in gmem (in-kernel split); C = Ah*Bh^T + Ah*Bl^T + Al*Bh^T.
// MODE==2: A exact bf16 in gmem; C = A*Bh^T + A*Bl^T.
// EPI==0: plain fp32 C store (+split-K z offset)      [basal]
// EPI==1: MC-neuron epilogue. C rows ordered (bs,t): A row remap
//         r -> (r&7)*NBS + (r>>3). acc -> smem -> per-element time recurrence
//         -> bf16 spikes to g_spall (bs,t layout). No C traffic.   [apical]
// EPI==2: LIF+readout epilogue. Rows already (bs,t) (spall layout).
//         acc -> smem -> ml recurrence + W2 partial readout -> g_opart. [h]
// CTA tile BM x 128, BK=32, 256 threads, 4-stage pipeline (dist 3, wait 2).
#define BKT 32
#define NSTG 4

template<int MODE, int BM, int EPI>
__global__ void __launch_bounds__(256, 2)
hmma_fused(const void* __restrict__ Araw,
           const __nv_bfloat16* __restrict__ Bh, const __nv_bfloat16* __restrict__ Bl,
           int kChunk, int lda, int Ntot, float* __restrict__ C, int M,
           const float* __restrict__ b1, const float* __restrict__ W2)
{
    extern __shared__ __nv_bfloat16 dsm[];
    constexpr int TILE_A = BM * BKT;
    constexpr int TILE_B = 128 * BKT;
    constexpr int NTA    = (MODE == 3) ? 2 : 1;            // Ah,(Al)
    constexpr int STG    = NTA * TILE_A + 2 * TILE_B;
    constexpr int OFF_AL = TILE_A;
    constexpr int OFF_BH = NTA * TILE_A;
    constexpr int OFF_BL = OFF_BH + TILE_B;

    constexpr int WM   = BM / 32;        // 2 for BM=64
    constexpr int NCOL = 128 / (8 / WM); // 32 for BM=64
    constexpr int NJ   = NCOL / 8;       // 4
    constexpr int NP   = NCOL / 16;      // 2
    constexpr int AIT  = BM / 32;        // 2

    const int tid  = threadIdx.x;
    const int wid  = tid >> 5;
    const int lane = tid & 31;
    const int wm   = wid & (WM - 1);
    const int wn   = wid / WM;

    const int rowBase = blockIdx.y * BM;
    const int colBase = blockIdx.x * 128;
    const int kOff    = blockIdx.z * kChunk;
    const int NT      = kChunk / BKT;

    const uint32_t smemB = s2u(dsm);
    const float* A32        = (const float*)Araw;
    const __nv_bfloat16* A16 = (const __nv_bfloat16*)Araw;

    float acc[2][NJ][4];
#pragma unroll
    for (int mi = 0; mi < 2; mi++)
#pragma unroll
        for (int nj = 0; nj < NJ; nj++)
#pragma unroll
            for (int q = 0; q < 4; q++) acc[mi][nj][q] = 0.f;

    // A row remap for EPI==1 (C row r=(bs,t) <- te row (t, bs))
    auto mapRow = [&](int r) -> size_t {
        if (EPI == 1) return (size_t)(r & 7) * NBS + (r >> 3);
        return (size_t)r;
    };

    // ---- B producer (cp.async, bf16 hi+lo; B always 128 rows) ----
    auto issueB = [&](int kt) {
        const int s  = kt % NSTG;
        const int kl = kt * BKT + kOff;
        const uint32_t base = smemB + (uint32_t)(s * STG) * 2;
#pragma unroll
        for (int i = 0; i < 2; i++) {
            const int v = tid + i * 256;
            const int m = v >> 2, u = v & 3;
            const uint32_t so = (uint32_t)(m * 64 + ((u ^ ((m >> 1) & 3)) << 4));
            const size_t gb = (size_t)(colBase + m) * lda + kl + u * 8;
            cp16(base + OFF_BH * 2 + so, Bh + gb);
            cp16(base + OFF_BL * 2 + so, Bl + gb);
        }
    };
    // ---- A producer, MODE2: exact bf16 via cp.async (rows linear) ----
    auto issueA2 = [&](int kt) {
        const int s  = kt % NSTG;
        const int kl = kt * BKT + kOff;
        const uint32_t base = smemB + (uint32_t)(s * STG) * 2;
        const int v = tid;
        const int m = v >> 2, u = v & 3;
        if (m < BM) {
            const uint32_t so = (uint32_t)(m * 64 + ((u ^ ((m >> 1) & 3)) << 4));
            cp16(base + so, A16 + (size_t)(rowBase + m) * lda + kl + u * 8);
        }
    };
    // ---- A producer, MODE3: LDG fp32 into regs (R5 ordering) ----
    auto ldgA = [&](int kt, float4* f) {
#pragma unroll
        for (int i = 0; i < AIT; i++) {
            const int fv = tid + i * 256;
            const int row = fv >> 3, u4 = fv & 7;
            f[i] = *(const float4*)(A32 + mapRow(rowBase + row) * lda
                                    + kt * BKT + kOff + u4 * 4);
        }
    };
    auto stsA = [&](int kt, const float4* f) {
        const int s = kt % NSTG;
        char* base = (char*)dsm + (size_t)(s * STG) * 2;
#pragma unroll
        for (int i = 0; i < AIT; i++) {
            const int fv = tid + i * 256;
            const int row = fv >> 3, u4 = fv & 7;
            const int u = u4 >> 1, half = u4 & 1;
            const uint32_t so = (uint32_t)(row * 64 + ((u ^ ((row >> 1) & 3)) << 4) + half * 8);
            uint2 hi, lo;
            split4(f[i], hi, lo);
            *(uint2*)(base + so)              = hi;
            *(uint2*)(base + OFF_AL * 2 + so) = lo;
        }
    };

    // ---- compute one BK=32 stage ----
    auto compute = [&](int s) {
        const uint32_t base = smemB + (uint32_t)(s * STG) * 2;
#pragma unroll
        for (int k16 = 0; k16 < 2; k16++) {
            uint32_t ah[2][4], al[2][4];
#pragma unroll
            for (int mi = 0; mi < 2; mi++) {
                const int row = wm * 32 + mi * 16 + (lane & 15);
                const int u   = k16 * 2 + (lane >> 4);
                const uint32_t off = (uint32_t)(row * 64 + ((u ^ ((row >> 1) & 3)) << 4));
                ldmx4(ah[mi], base + off);
                if (MODE == 3) ldmx4(al[mi], base + OFF_AL * 2 + off);
            }
#pragma unroll
            for (int np = 0; np < NP; np++) {
                const int n = wn * NCOL + np * 16 + ((lane >> 4) << 3) + (lane & 7);
                const int u = k16 * 2 + ((lane >> 3) & 1);
                const uint32_t boff = (uint32_t)(n * 64 + ((u ^ ((n >> 1) & 3)) << 4));
                uint32_t bh[4], bl[4];
                ldmx4(bh, base + OFF_BH * 2 + boff);
                ldmx4(bl, base + OFF_BL * 2 + boff);
                hmma(acc[0][2 * np],     ah[0], bh);
                hmma(acc[0][2 * np + 1], ah[0], bh + 2);
                hmma(acc[1][2 * np],     ah[1], bh);
                hmma(acc[1][2 * np + 1], ah[1], bh + 2);
                hmma(acc[0][2 * np],     ah[0], bl);
                hmma(acc[0][2 * np + 1], ah[0], bl + 2);
                hmma(acc[1][2 * np],     ah[1], bl);
                hmma(acc[1][2 * np + 1], ah[1], bl + 2);
                if (MODE == 3) {
                    hmma(acc[0][2 * np],     al[0], bh);
                    hmma(acc[0][2 * np + 1], al[0], bh + 2);
                    hmma(acc[1][2 * np],     al[1], bh);
                    hmma(acc[1][2 * np + 1], al[1], bh + 2);
                }
            }
        }
    };

    // ---- prologue: fill stages 0,1,2 ----
    float4 f[AIT];
#pragma unroll
    for (int p = 0; p < NSTG - 1; p++) {
        if (p < NT) {
            if (MODE == 3) { ldgA(p, f); stsA(p, f); } else { issueA2(p); }
            issueB(p);
        }
        cp_commit();
    }
    cp_wait2();
    __syncthreads();

    // ---- mainloop (R5-proven ordering) ----
    for (int kt = 0; kt < NT; kt++) {
        const bool pf = (kt + NSTG - 1 < NT);
        if (MODE == 3 && pf) ldgA(kt + NSTG - 1, f);
        if (pf) { if (MODE == 2) issueA2(kt + NSTG - 1); issueB(kt + NSTG - 1); }
        cp_commit();
        compute(kt % NSTG);
        if (MODE == 3 && pf) stsA(kt + NSTG - 1, f);
        cp_wait2();
        __syncthreads();
    }

    // ==================== epilogues ====================
    if (EPI == 0) {
        float* Cz = C + (size_t)blockIdx.z * M * Ntot;
#pragma unroll
        for (int mi = 0; mi < 2; mi++) {
            const int row = rowBase + wm * 32 + mi * 16 + (lane >> 2);
#pragma unroll
            for (int nj = 0; nj < NJ; nj++) {
                const int col = colBase + wn * NCOL + nj * 8 + (lane & 3) * 2;
                *(float2*)(Cz + (size_t)row * Ntot + col) =
                    make_float2(acc[mi][nj][0], acc[mi][nj][1]);
                *(float2*)(Cz + (size_t)(row + 8) * Ntot + col) =
                    make_float2(acc[mi][nj][2], acc[mi][nj][3]);
            }
        }
        return;
    }

    // stage acc tile to smem as fp32 [64][128]
    float* sC = (float*)dsm;
#pragma unroll
    for (int mi = 0; mi < 2; mi++) {
        const int row = wm * 32 + mi * 16 + (lane >> 2);
#pragma unroll
        for (int nj = 0; nj < NJ; nj++) {
            const int col = wn * NCOL + nj * 8 + (lane & 3) * 2;
            *(float2*)(sC + row * 128 + col) =
                make_float2(acc[mi][nj][0], acc[mi][nj][1]);
            *(float2*)(sC + (row + 8) * 128 + col) =
                make_float2(acc[mi][nj][2], acc[mi][nj][3]);
        }
    }
    __syncthreads();

    if (EPI == 1) {
        // MC-neuron recurrence: thread -> (bs_local, 4 f cols), loop t
        const int bsl = tid >> 5;
        const int fl  = (lane) * 4;
        const int bs_g = blockIdx.y * 8 + bsl;
        const int b    = bs_g >> 5;
        const int f_g  = colBase + fl;
        float4 mav = make_float4(0.f, 0.f, 0.f, 0.f);
        float4 msv = make_float4(0.f, 0.f, 0.f, 0.f);
#pragma unroll
        for (int t = 0; t < TSTEPS; t++) {
            float4 ap  = *(float4*)(sC + (bsl * 8 + t) * 128 + fl);
            float4 mbv = *(const float4*)(g_mball + t * NB * NF + b * NF + f_g);
            float4 spv;
            mav.x += (ap.x - mav.x) * 0.5f;
            msv.x += (mav.x + mbv.x - msv.x) * 0.5f;
            spv.x = (msv.x > 1.0f) ? 1.f : 0.f;  msv.x *= (1.f - spv.x);
            mav.y += (ap.y - mav.y) * 0.5f;
            msv.y += (mav.y + mbv.y - msv.y) * 0.5f;
            spv.y = (msv.y > 1.0f) ? 1.f : 0.f;  msv.y *= (1.f - spv.y);
            mav.z += (ap.z - mav.z) * 0.5f;
            msv.z += (mav.z + mbv.z - msv.z) * 0.5f;
            spv.z = (msv.z > 1.0f) ? 1.f : 0.f;  msv.z *= (1.f - spv.z);
            mav.w += (ap.w - mav.w) * 0.5f;
            msv.w += (mav.w + mbv.w - msv.w) * 0.5f;
            spv.w = (msv.w > 1.0f) ? 1.f : 0.f;  msv.w *= (1.f - spv.w);
            __nv_bfloat162* sp = (__nv_bfloat162*)
                (g_spall + (size_t)(bs_g * 8 + t) * NF + f_g);
            sp[0] = __halves2bfloat162(__float2bfloat16(spv.x), __float2bfloat16(spv.y));
            sp[1] = __halves2bfloat162(__float2bfloat16(spv.z), __float2bfloat16(spv.w));
        }
    } else {
        // EPI == 2: LIF recurrence + W2 readout partial (warp = one bs)
        const int bsl = tid >> 5;
        const int kl4 = lane * 4;
        const int bs_g = blockIdx.y * 8 + bsl;
        const int k_g  = colBase + kl4;
        float ml4[4] = {0.f, 0.f, 0.f, 0.f};
        float a[NL];
#pragma unroll
        for (int l = 0; l < NL; l++) a[l] = 0.f;
        const float b10 = b1[k_g], b11 = b1[k_g + 1], b12 = b1[k_g + 2], b13 = b1[k_g + 3];
#pragma unroll
        for (int t = 0; t < TSTEPS; t++) {
            float4 h4 = *(float4*)(sC + (bsl * 8 + t) * 128 + kl4);
            float hv[4] = { h4.x + b10, h4.y + b11, h4.z + b12, h4.w + b13 };
#pragma unroll
            for (int j = 0; j < 4; j++) {
                float m = ml4[j];
                m += (hv[j] - m) * 0.5f;
                const float s = (m > 0.5f) ? 1.f : 0.f;
                ml4[j] = m * (1.f - s);
                if (s != 0.f) {
#pragma unroll
                    for (int l = 0; l < NL; l++) a[l] += W2[l * NH + k_g + j];
                }
            }
        }
#pragma unroll
        for (int l = 0; l < NL; l++) {
#pragma unroll
            for (int o = 16; o; o >>= 1) a[l] += __shfl_xor_sync(0xffffffffu, a[l], o);
        }
        if (lane == 0) {
#pragma unroll
            for (int l = 0; l < NL; l++)
                g_opart[(size_t)blockIdx.x * NBS * NL + bs_g * NL + l] = a[l];
        }
    }
}

// =========================== small kernels ==================================
#define NWA (NF * NK / 4)
#define NW1 (NH * NF / 4)
__global__ void split_all(const float* __restrict__ Wa, const float* __restrict__ Wb,
                          const float* __restrict__ W1)
{
    const int i = blockIdx.x * blockDim.x + threadIdx.x;
    const float* src;
    __nv_bfloat16 *hi, *lo;
    int j = i;
    if (i < NWA)            { src = Wa; hi = g_Wah; lo = g_Wal; }
    else if (i < 2 * NWA)   { src = Wb; hi = g_Wbh; lo = g_Wbl; j = i - NWA; }
    else if (i < 2 * NWA + NW1) { src = W1; hi = g_W1h; lo = g_W1l; j = i - 2 * NWA; }
    else return;
    float4 v = ((const float4*)src)[j];
    uint2 h, l;
    split4(v, h, l);
    ((uint2*)hi)[j] = h;
    ((uint2*)lo)[j] = l;
}

__global__ void reduce_basal_mb()
{
    const int i = blockIdx.x * blockDim.x + threadIdx.x;   // over NB*NF
    if (i >= NB * NF) return;
    float mb = 0.f;
#pragma unroll
    for (int t = 0; t < TSTEPS; t++) {
        const int e = t * NB * NF + i;
        float s = 0.f;
#pragma unroll
        for (int p = 0; p < KSB; p++) s += g_bpart[(size_t)p * (TSTEPS * NB * NF) + e];
        mb += (s - mb) * 0.5f;
        g_mball[e] = mb;
    }
}

// final: out[b,l,s] = (sum of 4 k-chunk partials)/T + b2
__global__ void final_out(const float* __restrict__ b2, float* __restrict__ out)
{
    const int i = blockIdx.x * blockDim.x + threadIdx.x;
    if (i >= NB * NL * NS) return;
    const int s = i % NS;
    const int l = (i / NS) % NL;
    const int b = i / (NS * NL);
    const int bs = b * NS + s;
    float a = 0.f;
#pragma unroll
    for (int c = 0; c < 4; c++) a += g_opart[(size_t)c * NBS * NL + bs * NL + l];
    out[i] = a * (1.f / TSTEPS) + b2[l];
}

// ---------------------------------------------------------------------------
extern "C" void kernel_launch(void* const* d_in, const int* in_sizes, int n_in,
                              void* d_out, int out_size)
{
    (void)in_sizes; (void)n_in; (void)out_size;
    const float* se = (const float*)d_in[0];
    const float* te = (const float*)d_in[1];
    const float* Wb = (const float*)d_in[2];
    const float* Wa = (const float*)d_in[3];
    const float* W1 = (const float*)d_in[4];
    const float* b1 = (const float*)d_in[5];
    const float* W2 = (const float*)d_in[6];
    const float* b2 = (const float*)d_in[7];
    float* out = (float*)d_out;

    float* bpart;
    __nv_bfloat16 *Wah, *Wal, *Wbh, *Wbl, *W1h, *W1l, *spall;
    cudaGetSymbolAddress((void**)&bpart,  g_bpart);
    cudaGetSymbolAddress((void**)&Wah,    g_Wah);
    cudaGetSymbolAddress((void**)&Wal,    g_Wal);
    cudaGetSymbolAddress((void**)&Wbh,    g_Wbh);
    cudaGetSymbolAddress((void**)&Wbl,    g_Wbl);
    cudaGetSymbolAddress((void**)&W1h,    g_W1h);
    cudaGetSymbolAddress((void**)&W1l,    g_W1l);
    cudaGetSymbolAddress((void**)&spall,  g_spall);

    const int SMEM_M3 = (2 * 64 * BKT + 2 * 128 * BKT) * 2 * NSTG;   // 98304
    const int SMEM_M2 = (64 * BKT + 2 * 128 * BKT) * 2 * NSTG;       // 81920
    cudaFuncSetAttribute((const void*)hmma_fused<3, 64, 0>,
                         cudaFuncAttributeMaxDynamicSharedMemorySize, SMEM_M3);
    cudaFuncSetAttribute((const void*)hmma_fused<3, 64, 1>,
                         cudaFuncAttributeMaxDynamicSharedMemorySize, SMEM_M3);
    cudaFuncSetAttribute((const void*)hmma_fused<2, 64, 2>,
                         cudaFuncAttributeMaxDynamicSharedMemorySize, SMEM_M2);

    // weight hi/lo splits (one launch; te/se split in-kernel)
    split_all<<<(2 * NWA + NW1 + 255) / 256, 256>>>(Wa, Wb, W1);

    // basal: plain epilogue, split-K=7
    hmma_fused<3, 64, 0><<<dim3(NF / 128, (TSTEPS * NB) / 64, KSB), 256, SMEM_M3>>>(
        se, Wbh, Wbl, KCH_B, NK, NF, bpart, TSTEPS * NB, nullptr, nullptr);
    reduce_basal_mb<<<(NB * NF + 255) / 256, 256>>>();

    // apical GEMM + fused MC epilogue: rows (bs,t); writes spikes directly
    hmma_fused<3, 64, 1><<<dim3(NF / 128, (TSTEPS * NBS) / 64, 1), 256, SMEM_M3>>>(
        te, Wah, Wal, NK, NK, NF, nullptr, TSTEPS * NBS, nullptr, nullptr);

    // h GEMM + fused LIF/readout epilogue: A = spikes (bs,t rows)
    hmma_fused<2, 64, 2><<<dim3(NH / 128, (TSTEPS * NBS) / 64, 1), 256, SMEM_M2>>>(
        spall, W1h, W1l, NF, NF, NH, nullptr, TSTEPS * NBS, b1, W2);

    // reduce 4 readout partials + bias + reorder
    final_out<<<(NB * NL * NS + 255) / 256, 256>>>(b2, out);
}